// round 1
// baseline (speedup 1.0000x reference)
#include <cuda_runtime.h>
#include <cstdint>
#include <math.h>

#define N_NODES 100000
#define N_EDGES 3200000
#define D_FEAT 64
#define NUM_RELS 20
#define HID_ATTR 32
#define OUT_ATTR 10

#define SCAN_CHUNK 1024
#define SCAN_BLOCKS 98           // ceil(100000/1024)
#define SCAN_PAD (SCAN_BLOCKS * SCAN_CHUNK)

// ---------------- scratch (device globals; no allocation allowed) ----------------
__device__ float g_T[(size_t)NUM_RELS * N_NODES * D_FEAT];   // 512 MB transformed features
__device__ float g_H1[(size_t)N_NODES * D_FEAT];             // hidden layer output
__device__ int   g_cnt[N_NODES];
__device__ int   g_fill[N_NODES];
__device__ int   g_rowptr[N_NODES + 1];
__device__ int   g_scan[SCAN_PAD];
__device__ int   g_bsums[SCAN_BLOCKS];
__device__ int   g_boff[SCAN_BLOCKS];
__device__ int   g_eidx[N_EDGES];                            // sorted-by-dst: etype*N + src
__device__ float g_sum[D_FEAT];                              // column sums of h2

// ---------------- f32x2 packed FMA helpers ----------------
__device__ __forceinline__ unsigned long long pack2(float x, float y) {
    unsigned long long r;
    asm("mov.b64 %0, {%1, %2};" : "=l"(r) : "f"(x), "f"(y));
    return r;
}
__device__ __forceinline__ void ffma2(unsigned long long& d, unsigned long long a, unsigned long long b) {
    asm("fma.rn.f32x2 %0, %1, %2, %0;" : "+l"(d) : "l"(a), "l"(b));
}
__device__ __forceinline__ float2 unpack2(unsigned long long v) {
    float2 f;
    asm("mov.b64 {%0, %1}, %2;" : "=f"(f.x), "=f"(f.y) : "l"(v));
    return f;
}

// ---------------- kernels ----------------
__global__ void k_zero() {
    int i = blockIdx.x * blockDim.x + threadIdx.x;
    if (i < N_NODES) { g_cnt[i] = 0; g_fill[i] = 0; }
    if (blockIdx.x == 0 && threadIdx.x < D_FEAT) g_sum[threadIdx.x] = 0.0f;
}

__global__ void k_count(const int* __restrict__ dst) {
    int e = blockIdx.x * blockDim.x + threadIdx.x;
    if (e < N_EDGES) atomicAdd(&g_cnt[dst[e]], 1);
}

__global__ void k_scan1() {
    __shared__ int sm[256];
    int t = threadIdx.x;
    int base = blockIdx.x * SCAN_CHUNK;
    int v[4];
    int local = 0;
#pragma unroll
    for (int c = 0; c < 4; c++) {
        int idx = base + t * 4 + c;
        v[c] = (idx < N_NODES) ? g_cnt[idx] : 0;
        local += v[c];
    }
    sm[t] = local;
    __syncthreads();
    for (int off = 1; off < 256; off <<= 1) {
        int x = sm[t];
        int y = (t >= off) ? sm[t - off] : 0;
        __syncthreads();
        sm[t] = x + y;
        __syncthreads();
    }
    int run = sm[t] - local;   // exclusive prefix of this thread
#pragma unroll
    for (int c = 0; c < 4; c++) {
        run += v[c];
        g_scan[base + t * 4 + c] = run;   // inclusive scan within chunk
    }
    if (t == 255) g_bsums[blockIdx.x] = sm[255];
}

__global__ void k_scan2() {
    __shared__ int s[128];
    int t = threadIdx.x;
    s[t] = (t < SCAN_BLOCKS) ? g_bsums[t] : 0;
    __syncthreads();
    if (t == 0) {
        int acc = 0;
        for (int i = 0; i < SCAN_BLOCKS; i++) { int x = s[i]; s[i] = acc; acc += x; }
    }
    __syncthreads();
    if (t < SCAN_BLOCKS) g_boff[t] = s[t];
}

__global__ void k_scan3() {
    int i = blockIdx.x * blockDim.x + threadIdx.x;
    if (i < N_NODES) g_rowptr[i + 1] = g_scan[i] + g_boff[i >> 10];
    if (i == 0) g_rowptr[0] = 0;
}

__global__ void k_fill(const int* __restrict__ src, const int* __restrict__ dst,
                       const int* __restrict__ etype) {
    int e = blockIdx.x * blockDim.x + threadIdx.x;
    if (e < N_EDGES) {
        int d = dst[e];
        int pos = g_rowptr[d] + atomicAdd(&g_fill[d], 1);
        g_eidx[pos] = etype[e] * N_NODES + src[e];
    }
}

// T[r, m, :] = X[m, :] @ W[r]   (X: [n,64] row-major, W[r]: [64,64] row-major d->o)
__global__ void __launch_bounds__(256) k_rgemm(const float* __restrict__ X,
                                               const float* __restrict__ W,
                                               float* __restrict__ T) {
    __shared__ float Xs[128][64];   // 32 KB, row-major (m, k)
    __shared__ float Ws[64][64];    // 16 KB, (k, o)
    const int tx = threadIdx.x, ty = threadIdx.y;
    const int tid = ty * 16 + tx;
    const int m0 = blockIdx.x * 128;
    const int r = blockIdx.y;

    // load X tile (guard tail), float4 per slot
#pragma unroll
    for (int i = 0; i < 8; i++) {
        int f = i * 256 + tid;       // 0..2047 float4 slots
        int m = f >> 4;
        int k = (f & 15) << 2;
        float4 v = make_float4(0.f, 0.f, 0.f, 0.f);
        if (m0 + m < N_NODES) v = *(const float4*)(X + (size_t)(m0 + m) * 64 + k);
        *(float4*)&Xs[m][k] = v;
    }
    const float* Wr = W + (size_t)r * 4096;
#pragma unroll
    for (int i = 0; i < 4; i++) {
        int f = i * 256 + tid;       // 0..1023 float4 slots
        int k = f >> 4;
        int c = (f & 15) << 2;
        *(float4*)&Ws[k][c] = *(const float4*)(Wr + k * 64 + c);
    }
    __syncthreads();

    unsigned long long z[8][2];
#pragma unroll
    for (int i = 0; i < 8; i++) { z[i][0] = 0ull; z[i][1] = 0ull; }

#pragma unroll 4
    for (int k = 0; k < 64; k += 4) {
        unsigned long long b[4][2];
#pragma unroll
        for (int kk = 0; kk < 4; kk++) {
            b[kk][0] = *(const unsigned long long*)&Ws[k + kk][tx * 4];
            b[kk][1] = *(const unsigned long long*)&Ws[k + kk][tx * 4 + 2];
        }
#pragma unroll
        for (int i = 0; i < 8; i++) {
            float4 a = *(const float4*)&Xs[ty * 8 + i][k];
            unsigned long long a0 = pack2(a.x, a.x);
            unsigned long long a1 = pack2(a.y, a.y);
            unsigned long long a2 = pack2(a.z, a.z);
            unsigned long long a3 = pack2(a.w, a.w);
            ffma2(z[i][0], a0, b[0][0]); ffma2(z[i][1], a0, b[0][1]);
            ffma2(z[i][0], a1, b[1][0]); ffma2(z[i][1], a1, b[1][1]);
            ffma2(z[i][0], a2, b[2][0]); ffma2(z[i][1], a2, b[2][1]);
            ffma2(z[i][0], a3, b[3][0]); ffma2(z[i][1], a3, b[3][1]);
        }
    }

#pragma unroll
    for (int i = 0; i < 8; i++) {
        int m = m0 + ty * 8 + i;
        if (m < N_NODES) {
            float2 lo = unpack2(z[i][0]);
            float2 hi = unpack2(z[i][1]);
            float4 o = make_float4(lo.x, lo.y, hi.x, hi.y);
            *(float4*)(T + ((size_t)r * N_NODES + m) * 64 + tx * 4) = o;
        }
    }
}

// warp per node: acc = sum_{edges into node} T[eidx(e)][:]  (optionally relu), coalesced float2
template <bool RELU>
__global__ void k_agg(const float* __restrict__ T, float* __restrict__ out) {
    int gw = (blockIdx.x * blockDim.x + threadIdx.x) >> 5;
    int lane = threadIdx.x & 31;
    if (gw >= N_NODES) return;
    int s = g_rowptr[gw];
    int e = g_rowptr[gw + 1];
    float2 acc = make_float2(0.f, 0.f);
#pragma unroll 4
    for (int i = s; i < e; i++) {
        int row = g_eidx[i];
        float2 v = *((const float2*)(T + (size_t)row * 64) + lane);
        acc.x += v.x;
        acc.y += v.y;
    }
    if (RELU) { acc.x = fmaxf(acc.x, 0.f); acc.y = fmaxf(acc.y, 0.f); }
    *((float2*)(out + (size_t)gw * 64) + lane) = acc;
}

__global__ void k_reduce(const float* __restrict__ h2) {
    __shared__ float sm[D_FEAT];
    int t = threadIdx.x;
    if (t < D_FEAT) sm[t] = 0.f;
    __syncthreads();
    float acc = 0.f;
    const long total = (long)N_NODES * D_FEAT;
    for (long i = (long)blockIdx.x * blockDim.x + t; i < total; i += (long)gridDim.x * blockDim.x)
        acc += h2[i];
    atomicAdd(&sm[t & 63], acc);   // stride is a multiple of 64 -> each thread's dim fixed
    __syncthreads();
    if (t < D_FEAT) atomicAdd(&g_sum[t], sm[t]);
}

__global__ void k_mlp(const float* __restrict__ A1w, const float* __restrict__ A1b,
                      const float* __restrict__ A2w, const float* __restrict__ A2b,
                      float* __restrict__ out_a) {
    __shared__ float g[D_FEAT];
    __shared__ float a1[HID_ATTR];
    int t = threadIdx.x;
    if (t < D_FEAT) g[t] = g_sum[t] * (1.0f / (float)N_NODES);
    __syncthreads();
    if (t < HID_ATTR) {
        float s = A1b[t];
#pragma unroll
        for (int k = 0; k < D_FEAT; k++) s += g[k] * A1w[k * HID_ATTR + t];
        a1[t] = fmaxf(s, 0.f);
    }
    __syncthreads();
    if (t < OUT_ATTR) {
        float s = A2b[t];
#pragma unroll
        for (int k = 0; k < HID_ATTR; k++) s += a1[k] * A2w[k * OUT_ATTR + t];
        out_a[t] = 1.0f / (1.0f + expf(-s));
    }
}

// ---------------- launch ----------------
extern "C" void kernel_launch(void* const* d_in, const int* in_sizes, int n_in,
                              void* d_out, int out_size) {
    const float* h     = (const float*)d_in[0];
    const int*   src   = (const int*)d_in[1];
    const int*   dst   = (const int*)d_in[2];
    const int*   etype = (const int*)d_in[3];
    const float* W1    = (const float*)d_in[4];
    const float* W2    = (const float*)d_in[5];
    const float* A1w   = (const float*)d_in[6];
    const float* A1b   = (const float*)d_in[7];
    const float* A2w   = (const float*)d_in[8];
    const float* A2b   = (const float*)d_in[9];
    float* out = (float*)d_out;

    float* T;   cudaGetSymbolAddress((void**)&T,  g_T);
    float* H1;  cudaGetSymbolAddress((void**)&H1, g_H1);

    const int EB = (N_EDGES + 255) / 256;          // 12500
    const int NB = (N_NODES + 255) / 256;          // 391

    // CSR build (shared by both layers)
    k_zero<<<NB, 256>>>();
    k_count<<<EB, 256>>>(dst);
    k_scan1<<<SCAN_BLOCKS, 256>>>();
    k_scan2<<<1, 128>>>();
    k_scan3<<<(N_NODES + 256) / 256, 256>>>();
    k_fill<<<EB, 256>>>(src, dst, etype);

    dim3 gemm_grid((N_NODES + 127) / 128, NUM_RELS);
    dim3 gemm_block(16, 16);
    const int AGG_BLOCKS = (N_NODES * 32 + 255) / 256;   // warp per node, 8 warps/block

    // layer 1: transform + aggregate (relu)
    k_rgemm<<<gemm_grid, gemm_block>>>(h, W1, T);
    k_agg<true><<<AGG_BLOCKS, 256>>>(T, H1);

    // layer 2: transform + aggregate (no activation) -> h2 straight into d_out
    k_rgemm<<<gemm_grid, gemm_block>>>(H1, W2, T);
    k_agg<false><<<AGG_BLOCKS, 256>>>(T, out);

    // graph mean + attributor MLP -> last 10 floats of d_out
    k_reduce<<<256, 256>>>(out);
    k_mlp<<<1, 64>>>(A1w, A1b, A2w, A2b, out + (size_t)N_NODES * D_FEAT);
}

// round 3
// speedup vs baseline: 1.4347x; 1.4347x over previous
#include <cuda_runtime.h>
#include <cstdint>
#include <math.h>

#define N_NODES 100000
#define N_EDGES 3200000
#define D_FEAT 64
#define NUM_RELS 20
#define HID_ATTR 32
#define OUT_ATTR 10

#define SCAN_CHUNK 1024
#define SCAN_BLOCKS 98           // ceil(100000/1024)
#define SCAN_PAD (SCAN_BLOCKS * SCAN_CHUNK)

// ---------------- scratch (device globals; no allocation allowed) ----------------
__device__ float g_T[(size_t)NUM_RELS * N_NODES * D_FEAT];   // 512 MB transformed features
__device__ float g_H1[(size_t)N_NODES * D_FEAT];             // hidden layer output
__device__ int   g_cnt[N_NODES];
__device__ int   g_fill[N_NODES];
__device__ int   g_rowptr[N_NODES + 1];
__device__ int   g_scan[SCAN_PAD];
__device__ int   g_bsums[SCAN_BLOCKS];
__device__ int   g_boff[SCAN_BLOCKS];
__device__ int   g_eidx[N_EDGES];                            // sorted-by-dst: etype*N + src
__device__ float g_sum[D_FEAT];                              // column sums of h2

__device__ __forceinline__ uint32_t f2tf32(float x) {
    uint32_t r; asm("cvt.rna.tf32.f32 %0, %1;" : "=r"(r) : "f"(x)); return r;
}

// ---------------- kernels ----------------
__global__ void k_zero() {
    int i = blockIdx.x * blockDim.x + threadIdx.x;
    if (i < N_NODES) { g_cnt[i] = 0; g_fill[i] = 0; }
    if (blockIdx.x == 0 && threadIdx.x < D_FEAT) g_sum[threadIdx.x] = 0.0f;
}

__global__ void k_count(const int* __restrict__ dst) {
    int e = blockIdx.x * blockDim.x + threadIdx.x;
    if (e < N_EDGES) atomicAdd(&g_cnt[dst[e]], 1);
}

__global__ void k_scan1() {
    __shared__ int sm[256];
    int t = threadIdx.x;
    int base = blockIdx.x * SCAN_CHUNK;
    int v[4];
    int local = 0;
#pragma unroll
    for (int c = 0; c < 4; c++) {
        int idx = base + t * 4 + c;
        v[c] = (idx < N_NODES) ? g_cnt[idx] : 0;
        local += v[c];
    }
    sm[t] = local;
    __syncthreads();
    for (int off = 1; off < 256; off <<= 1) {
        int x = sm[t];
        int y = (t >= off) ? sm[t - off] : 0;
        __syncthreads();
        sm[t] = x + y;
        __syncthreads();
    }
    int run = sm[t] - local;
#pragma unroll
    for (int c = 0; c < 4; c++) {
        run += v[c];
        g_scan[base + t * 4 + c] = run;
    }
    if (t == 255) g_bsums[blockIdx.x] = sm[255];
}

__global__ void k_scan2() {
    __shared__ int s[128];
    int t = threadIdx.x;
    s[t] = (t < SCAN_BLOCKS) ? g_bsums[t] : 0;
    __syncthreads();
    if (t == 0) {
        int acc = 0;
        for (int i = 0; i < SCAN_BLOCKS; i++) { int x = s[i]; s[i] = acc; acc += x; }
    }
    __syncthreads();
    if (t < SCAN_BLOCKS) g_boff[t] = s[t];
}

__global__ void k_scan3() {
    int i = blockIdx.x * blockDim.x + threadIdx.x;
    if (i < N_NODES) g_rowptr[i + 1] = g_scan[i] + g_boff[i >> 10];
    if (i == 0) g_rowptr[0] = 0;
}

__global__ void k_fill(const int* __restrict__ src, const int* __restrict__ dst,
                       const int* __restrict__ etype) {
    int e = blockIdx.x * blockDim.x + threadIdx.x;
    if (e < N_EDGES) {
        int d = dst[e];
        int pos = g_rowptr[d] + atomicAdd(&g_fill[d], 1);
        g_eidx[pos] = etype[e] * N_NODES + src[e];
    }
}

// T[r, m, :] = X[m, :] @ W[r] for all 20 relations.
// tf32 mma.sync (m16n8k8), CTA = 128 rows x 64 cols, 8 warps (16 rows each).
// X tile staged once; A-fragments live in registers for the whole kernel.
// dynamic smem layout: Xs = uint32[128*64] (tf32 bits), Ws = uint32[64*72]
#define XS_WORDS (128 * 64)
#define WS_STRIDE 72
#define MG_SMEM_BYTES ((XS_WORDS + 64 * WS_STRIDE) * 4)

__global__ void __launch_bounds__(256) k_mgemm(const float* __restrict__ X,
                                               const float* __restrict__ W,
                                               float* __restrict__ T) {
    extern __shared__ uint32_t sm_u[];
    uint32_t* Xs = sm_u;                 // [row][k], stride 64
    uint32_t* Ws = sm_u + XS_WORDS;      // [k][n],  stride 72 (conflict-free B frags)

    const int tid = threadIdx.x;
    const int wid = tid >> 5;
    const int lane = tid & 31;
    const int g = lane >> 2;             // groupID (0..7)
    const int t4 = lane & 3;             // threadID_in_group (0..3)
    const int m0 = blockIdx.x * 128;

    // stage X tile (tf32), zero-padded tail
#pragma unroll
    for (int i = 0; i < 8; i++) {
        int f = i * 256 + tid;           // float4 slot 0..2047
        int row = f >> 4;
        int k4 = (f & 15) << 2;
        float4 v = make_float4(0.f, 0.f, 0.f, 0.f);
        if (m0 + row < N_NODES) v = *(const float4*)(X + (size_t)(m0 + row) * 64 + k4);
        uint4 u;
        u.x = f2tf32(v.x); u.y = f2tf32(v.y); u.z = f2tf32(v.z); u.w = f2tf32(v.w);
        *(uint4*)(Xs + row * 64 + k4) = u;
    }
    __syncthreads();

    // hoist A fragments: rows wid*16 + {g, g+8}, k covered by 8 k-steps
    uint32_t a[8][4];
    const int ar0 = wid * 16 + g;
#pragma unroll
    for (int kt = 0; kt < 8; kt++) {
        int kb = kt * 8;
        a[kt][0] = Xs[ar0 * 64 + kb + t4];
        a[kt][1] = Xs[(ar0 + 8) * 64 + kb + t4];
        a[kt][2] = Xs[ar0 * 64 + kb + t4 + 4];
        a[kt][3] = Xs[(ar0 + 8) * 64 + kb + t4 + 4];
    }

    const int m_lo = m0 + ar0;
    const int m_hi = m_lo + 8;

    for (int r = 0; r < NUM_RELS; r++) {
        __syncthreads();     // previous relation's B reads done; safe to overwrite
        const float* Wr = W + (size_t)r * 4096;
#pragma unroll
        for (int i = 0; i < 4; i++) {
            int f = i * 256 + tid;       // float4 slot 0..1023
            int krow = f >> 4;           // k (0..63)
            int n4 = (f & 15) << 2;      // n base
            float4 v = *(const float4*)(Wr + krow * 64 + n4);
            uint4 u;
            u.x = f2tf32(v.x); u.y = f2tf32(v.y); u.z = f2tf32(v.z); u.w = f2tf32(v.w);
            *(uint4*)(Ws + krow * WS_STRIDE + n4) = u;
        }
        __syncthreads();

        float c[8][4];
#pragma unroll
        for (int nt = 0; nt < 8; nt++) { c[nt][0] = 0.f; c[nt][1] = 0.f; c[nt][2] = 0.f; c[nt][3] = 0.f; }

#pragma unroll
        for (int kt = 0; kt < 8; kt++) {
            int kb = kt * 8 + t4;
            uint32_t b[8][2];
#pragma unroll
            for (int nt = 0; nt < 8; nt++) {
                int n = nt * 8 + g;
                b[nt][0] = Ws[kb * WS_STRIDE + n];
                b[nt][1] = Ws[(kb + 4) * WS_STRIDE + n];
            }
#pragma unroll
            for (int nt = 0; nt < 8; nt++) {
                asm volatile(
                    "mma.sync.aligned.m16n8k8.row.col.f32.tf32.tf32.f32 "
                    "{%0,%1,%2,%3}, {%4,%5,%6,%7}, {%8,%9}, {%0,%1,%2,%3};"
                    : "+f"(c[nt][0]), "+f"(c[nt][1]), "+f"(c[nt][2]), "+f"(c[nt][3])
                    : "r"(a[kt][0]), "r"(a[kt][1]), "r"(a[kt][2]), "r"(a[kt][3]),
                      "r"(b[nt][0]), "r"(b[nt][1]));
            }
        }

        float* base = T + (size_t)r * N_NODES * 64;
#pragma unroll
        for (int nt = 0; nt < 8; nt++) {
            int col = nt * 8 + t4 * 2;
            if (m_lo < N_NODES) *(float2*)(base + (size_t)m_lo * 64 + col) = make_float2(c[nt][0], c[nt][1]);
            if (m_hi < N_NODES) *(float2*)(base + (size_t)m_hi * 64 + col) = make_float2(c[nt][2], c[nt][3]);
        }
    }
}

// warp per node: acc = sum_{edges into node} T[eidx(e)][:]  (optionally relu), coalesced float2
template <bool RELU>
__global__ void k_agg(const float* __restrict__ T, float* __restrict__ out) {
    int gw = (blockIdx.x * blockDim.x + threadIdx.x) >> 5;
    int lane = threadIdx.x & 31;
    if (gw >= N_NODES) return;
    int s = g_rowptr[gw];
    int e = g_rowptr[gw + 1];
    float2 acc = make_float2(0.f, 0.f);
#pragma unroll 4
    for (int i = s; i < e; i++) {
        int row = g_eidx[i];
        float2 v = *((const float2*)(T + (size_t)row * 64) + lane);
        acc.x += v.x;
        acc.y += v.y;
    }
    if (RELU) { acc.x = fmaxf(acc.x, 0.f); acc.y = fmaxf(acc.y, 0.f); }
    *((float2*)(out + (size_t)gw * 64) + lane) = acc;
}

__global__ void k_reduce(const float* __restrict__ h2) {
    __shared__ float sm[D_FEAT];
    int t = threadIdx.x;
    if (t < D_FEAT) sm[t] = 0.f;
    __syncthreads();
    float acc = 0.f;
    const long total = (long)N_NODES * D_FEAT;
    for (long i = (long)blockIdx.x * blockDim.x + t; i < total; i += (long)gridDim.x * blockDim.x)
        acc += h2[i];
    atomicAdd(&sm[t & 63], acc);
    __syncthreads();
    if (t < D_FEAT) atomicAdd(&g_sum[t], sm[t]);
}

__global__ void k_mlp(const float* __restrict__ A1w, const float* __restrict__ A1b,
                      const float* __restrict__ A2w, const float* __restrict__ A2b,
                      float* __restrict__ out_a) {
    __shared__ float g[D_FEAT];
    __shared__ float a1[HID_ATTR];
    int t = threadIdx.x;
    if (t < D_FEAT) g[t] = g_sum[t] * (1.0f / (float)N_NODES);
    __syncthreads();
    if (t < HID_ATTR) {
        float s = A1b[t];
#pragma unroll
        for (int k = 0; k < D_FEAT; k++) s += g[k] * A1w[k * HID_ATTR + t];
        a1[t] = fmaxf(s, 0.f);
    }
    __syncthreads();
    if (t < OUT_ATTR) {
        float s = A2b[t];
#pragma unroll
        for (int k = 0; k < HID_ATTR; k++) s += a1[k] * A2w[k * OUT_ATTR + t];
        out_a[t] = 1.0f / (1.0f + expf(-s));
    }
}

// ---------------- launch ----------------
extern "C" void kernel_launch(void* const* d_in, const int* in_sizes, int n_in,
                              void* d_out, int out_size) {
    const float* h     = (const float*)d_in[0];
    const int*   src   = (const int*)d_in[1];
    const int*   dst   = (const int*)d_in[2];
    const int*   etype = (const int*)d_in[3];
    const float* W1    = (const float*)d_in[4];
    const float* W2    = (const float*)d_in[5];
    const float* A1w   = (const float*)d_in[6];
    const float* A1b   = (const float*)d_in[7];
    const float* A2w   = (const float*)d_in[8];
    const float* A2b   = (const float*)d_in[9];
    float* out = (float*)d_out;

    float* T;   cudaGetSymbolAddress((void**)&T,  g_T);
    float* H1;  cudaGetSymbolAddress((void**)&H1, g_H1);

    cudaFuncSetAttribute(k_mgemm, cudaFuncAttributeMaxDynamicSharedMemorySize, MG_SMEM_BYTES);

    const int EB = (N_EDGES + 255) / 256;          // 12500
    const int NB = (N_NODES + 255) / 256;          // 391

    // CSR build (shared by both layers)
    k_zero<<<NB, 256>>>();
    k_count<<<EB, 256>>>(dst);
    k_scan1<<<SCAN_BLOCKS, 256>>>();
    k_scan2<<<1, 128>>>();
    k_scan3<<<(N_NODES + 256) / 256, 256>>>();
    k_fill<<<EB, 256>>>(src, dst, etype);

    const int GEMM_BLOCKS = (N_NODES + 127) / 128;       // 782
    const int AGG_BLOCKS = (N_NODES * 32 + 255) / 256;   // warp per node

    // layer 1: transform (tf32 mma.sync) + aggregate (relu)
    k_mgemm<<<GEMM_BLOCKS, 256, MG_SMEM_BYTES>>>(h, W1, T);
    k_agg<true><<<AGG_BLOCKS, 256>>>(T, H1);

    // layer 2: transform + aggregate (no activation) -> h2 straight into d_out
    k_mgemm<<<GEMM_BLOCKS, 256, MG_SMEM_BYTES>>>(H1, W2, T);
    k_agg<false><<<AGG_BLOCKS, 256>>>(T, out);

    // graph mean + attributor MLP -> last 10 floats of d_out
    k_reduce<<<256, 256>>>(out);
    k_mlp<<<1, 64>>>(A1w, A1b, A2w, A2b, out + (size_t)N_NODES * D_FEAT);
}